// round 1
// baseline (speedup 1.0000x reference)
#include <cuda_runtime.h>

// Problem constants
// B=8, C=256, H=W=128, IC=128, HEADS=8, WS=8, G=1, HD=16, NH=NW=16, N=64, BWIN=2048
#define HW 16384          // 128*128
#define NPIX 131072       // 8*16384
#define Z_ELEMS 33554432  // 8*256*16384
#define ATTN_ELEMS 69222400

// Scratch (allocation-free rule: __device__ globals)
__device__ float g_q[16777216];  // [win][head][tok][hd] = [2048][8][64][16]
__device__ float g_k[16777216];
__device__ float g_v[16777216];
__device__ float g_o[16777216];  // attention out, spatial [b][ic=128][h][w]

// ---------------------------------------------------------------------------
// QKV projection GEMM: out[oc][pix] = sum_c W[oc][c]*x[b][c][hw] + bias[oc]
// M=128, K=256, N=131072. Tile 128x64x16, 256 threads, thread tile 8x4.
// Writes directly in window-token layout.
// ---------------------------------------------------------------------------
__global__ void __launch_bounds__(256) gemm_qkv_kernel(
    const float* __restrict__ Wm, const float* __restrict__ bias,
    const float* __restrict__ x, int sel)
{
    __shared__ float As[16][128];
    __shared__ float Bs[16][64];
    float* out = (sel == 0) ? g_q : (sel == 1) ? g_k : g_v;

    const int tid = threadIdx.x;
    const int tx = tid & 15;   // 16 col groups * TN=4
    const int ty = tid >> 4;   // 16 row groups * TM=8
    const int n0 = blockIdx.x * 64;
    const int batch = n0 >> 14;
    const int hw0 = n0 & (HW - 1);
    const float* xb = x + (size_t)batch * 256 * HW + hw0;

    float acc[8][4];
#pragma unroll
    for (int i = 0; i < 8; i++)
#pragma unroll
        for (int j = 0; j < 4; j++) acc[i][j] = 0.f;

    for (int k0 = 0; k0 < 256; k0 += 16) {
#pragma unroll
        for (int l = 0; l < 2; l++) {
            int f = tid * 2 + l;            // 0..511 float4s of the 128x16 A tile
            int row = f >> 2;               // 0..127
            int kq = f & 3;                 // which float4 within the 16-wide k slab
            float4 v = *reinterpret_cast<const float4*>(&Wm[row * 256 + k0 + kq * 4]);
            As[kq * 4 + 0][row] = v.x;
            As[kq * 4 + 1][row] = v.y;
            As[kq * 4 + 2][row] = v.z;
            As[kq * 4 + 3][row] = v.w;
        }
        {
            int k = tid >> 4;               // 0..15
            int j4 = tid & 15;              // 0..15 float4s per row
            float4 v = *reinterpret_cast<const float4*>(&xb[(size_t)(k0 + k) * HW + j4 * 4]);
            *reinterpret_cast<float4*>(&Bs[k][j4 * 4]) = v;
        }
        __syncthreads();
#pragma unroll
        for (int k = 0; k < 16; k++) {
            float4 a0 = *reinterpret_cast<float4*>(&As[k][ty * 8]);
            float4 a1 = *reinterpret_cast<float4*>(&As[k][ty * 8 + 4]);
            float4 bv = *reinterpret_cast<float4*>(&Bs[k][tx * 4]);
            float a[8] = {a0.x, a0.y, a0.z, a0.w, a1.x, a1.y, a1.z, a1.w};
            float b[4] = {bv.x, bv.y, bv.z, bv.w};
#pragma unroll
            for (int i = 0; i < 8; i++)
#pragma unroll
                for (int j = 0; j < 4; j++) acc[i][j] += a[i] * b[j];
        }
        __syncthreads();
    }

#pragma unroll
    for (int i = 0; i < 8; i++) {
        int m = ty * 8 + i;                 // output channel 0..127
        float bv = __ldg(&bias[m]);
        int head = m >> 4, hd = m & 15;
#pragma unroll
        for (int j = 0; j < 4; j++) {
            int hw = hw0 + tx * 4 + j;
            int h = hw >> 7, w = hw & 127;
            int win = batch * 256 + (h >> 3) * 16 + (w >> 3);
            int tok = (h & 7) * 8 + (w & 7);
            out[(size_t)win * 8192 + head * 1024 + tok * 16 + hd] = acc[i][j] + bv;
        }
    }
}

// ---------------------------------------------------------------------------
// Attention: one block per (window, head). 65 rows (1 global + 64 tokens).
// scores/softmax in smem; attn probs written straight to d_out; AV -> g_o.
// ---------------------------------------------------------------------------
__global__ void __launch_bounds__(128) attn_kernel(
    const float* __restrict__ gtok, float* __restrict__ attn_out, int write_attn)
{
    __shared__ float Ks[65][16];
    __shared__ float Vs[65][16];
    __shared__ float S[65][66];

    const int tid = threadIdx.x;
    const int wh = blockIdx.x;       // win*8 + head
    const int head = wh & 7;
    const int win = wh >> 3;
    const size_t base = (size_t)wh * 1024;

    // load K,V token rows (64x16 each) as float4s
#pragma unroll
    for (int l = 0; l < 2; l++) {
        int f = tid + l * 128;       // 0..255 float4s
        int e = f * 4;
        int row = e >> 4;
        int col = e & 15;
        float4 kv = *reinterpret_cast<const float4*>(&g_k[base + e]);
        *reinterpret_cast<float4*>(&Ks[row + 1][col]) = kv;
        float4 vv = *reinterpret_cast<const float4*>(&g_v[base + e]);
        *reinterpret_cast<float4*>(&Vs[row + 1][col]) = vv;
    }
    if (tid < 4) {                   // global token row 0 (same values in k and v)
        float4 g = *reinterpret_cast<const float4*>(&gtok[head * 16 + tid * 4]);
        *reinterpret_cast<float4*>(&Ks[0][tid * 4]) = g;
        *reinterpret_cast<float4*>(&Vs[0][tid * 4]) = g;
    }
    __syncthreads();

    if (tid < 65) {
        float q[16];
        if (tid == 0) {
#pragma unroll
            for (int c = 0; c < 16; c++) q[c] = gtok[head * 16 + c];
        } else {
            const float* qp = &g_q[base + (size_t)(tid - 1) * 16];
#pragma unroll
            for (int c4 = 0; c4 < 4; c4++) {
                float4 v = *reinterpret_cast<const float4*>(&qp[c4 * 4]);
                q[c4 * 4 + 0] = v.x; q[c4 * 4 + 1] = v.y;
                q[c4 * 4 + 2] = v.z; q[c4 * 4 + 3] = v.w;
            }
        }
        float mx = -1e30f;
#pragma unroll 4
        for (int j = 0; j < 65; j++) {
            float d = 0.f;
#pragma unroll
            for (int c = 0; c < 16; c++) d += q[c] * Ks[j][c];
            d *= 0.25f;              // 1/sqrt(16)
            S[tid][j] = d;
            mx = fmaxf(mx, d);
        }
        float sum = 0.f;
#pragma unroll 4
        for (int j = 0; j < 65; j++) {
            float e = __expf(S[tid][j] - mx);
            S[tid][j] = e;
            sum += e;
        }
        float inv = 1.f / sum;
#pragma unroll 4
        for (int j = 0; j < 65; j++) S[tid][j] *= inv;
    }
    __syncthreads();

    if (write_attn) {
        float* ap = attn_out + (size_t)wh * 4225;
        for (int e = tid; e < 4225; e += 128) {
            int r = e / 65, c2 = e - r * 65;
            ap[e] = S[r][c2];
        }
    }

    // out = attn[:, 1:, :] @ V  -> g_o spatial. tok = tid&63 constant per thread.
    const int tok = tid & 63;
    const int b = win >> 8;
    const int wy = (win >> 4) & 15, wx = win & 15;
    const int h = wy * 8 + (tok >> 3), w = wx * 8 + (tok & 7);
#pragma unroll
    for (int i = 0; i < 8; i++) {
        int e = i * 128 + tid;       // 0..1023 = hd*64 + tok
        int hd = e >> 6;
        float a = 0.f;
#pragma unroll 5
        for (int j = 0; j < 65; j++) a += S[tok + 1][j] * Vs[j][hd];
        int oc = head * 16 + hd;
        g_o[(size_t)(b * 128 + oc) * HW + h * 128 + w] = a;
    }
}

// ---------------------------------------------------------------------------
// z = Wz @ g_o  (M=256, K=128, N=131072) + BatchNorm epilogue -> d_out
// ---------------------------------------------------------------------------
__global__ void __launch_bounds__(256) gemm_z_kernel(
    const float* __restrict__ Wz, const float* __restrict__ gamma,
    const float* __restrict__ beta, const float* __restrict__ mean,
    const float* __restrict__ var, float* __restrict__ out)
{
    __shared__ float As[16][128];
    __shared__ float Bs[16][64];

    const int tid = threadIdx.x;
    const int tx = tid & 15;
    const int ty = tid >> 4;
    const int n0 = blockIdx.x * 64;
    const int m0 = blockIdx.y * 128;
    const int batch = n0 >> 14;
    const int hw0 = n0 & (HW - 1);
    const float* xb = g_o + (size_t)batch * 128 * HW + hw0;

    float acc[8][4];
#pragma unroll
    for (int i = 0; i < 8; i++)
#pragma unroll
        for (int j = 0; j < 4; j++) acc[i][j] = 0.f;

    for (int k0 = 0; k0 < 128; k0 += 16) {
#pragma unroll
        for (int l = 0; l < 2; l++) {
            int f = tid * 2 + l;
            int row = f >> 2;
            int kq = f & 3;
            float4 v = *reinterpret_cast<const float4*>(&Wz[(m0 + row) * 128 + k0 + kq * 4]);
            As[kq * 4 + 0][row] = v.x;
            As[kq * 4 + 1][row] = v.y;
            As[kq * 4 + 2][row] = v.z;
            As[kq * 4 + 3][row] = v.w;
        }
        {
            int k = tid >> 4;
            int j4 = tid & 15;
            float4 v = *reinterpret_cast<const float4*>(&xb[(size_t)(k0 + k) * HW + j4 * 4]);
            *reinterpret_cast<float4*>(&Bs[k][j4 * 4]) = v;
        }
        __syncthreads();
#pragma unroll
        for (int k = 0; k < 16; k++) {
            float4 a0 = *reinterpret_cast<float4*>(&As[k][ty * 8]);
            float4 a1 = *reinterpret_cast<float4*>(&As[k][ty * 8 + 4]);
            float4 bv = *reinterpret_cast<float4*>(&Bs[k][tx * 4]);
            float a[8] = {a0.x, a0.y, a0.z, a0.w, a1.x, a1.y, a1.z, a1.w};
            float b[4] = {bv.x, bv.y, bv.z, bv.w};
#pragma unroll
            for (int i = 0; i < 8; i++)
#pragma unroll
                for (int j = 0; j < 4; j++) acc[i][j] += a[i] * b[j];
        }
        __syncthreads();
    }

#pragma unroll
    for (int i = 0; i < 8; i++) {
        int oc = m0 + ty * 8 + i;
        float sc = __ldg(&gamma[oc]) * rsqrtf(__ldg(&var[oc]) + 1e-5f);
        float sh = __ldg(&beta[oc]) - __ldg(&mean[oc]) * sc;
        float4 r;
        r.x = acc[i][0] * sc + sh;
        r.y = acc[i][1] * sc + sh;
        r.z = acc[i][2] * sc + sh;
        r.w = acc[i][3] * sc + sh;
        *reinterpret_cast<float4*>(&out[(size_t)(batch * 256 + oc) * HW + hw0 + tx * 4]) = r;
    }
}

// ---------------------------------------------------------------------------
extern "C" void kernel_launch(void* const* d_in, const int* in_sizes, int n_in,
                              void* d_out, int out_size)
{
    const float* x_this  = (const float*)d_in[0];
    const float* x_other = (const float*)d_in[1];
    const float* Wq = (const float*)d_in[2];
    const float* bq = (const float*)d_in[3];
    const float* Wk = (const float*)d_in[4];
    const float* bk = (const float*)d_in[5];
    const float* Wv = (const float*)d_in[6];
    const float* bv = (const float*)d_in[7];
    const float* gtok = (const float*)d_in[8];
    const float* Wz = (const float*)d_in[9];
    const float* gamma = (const float*)d_in[10];
    const float* beta  = (const float*)d_in[11];
    const float* mean  = (const float*)d_in[12];
    const float* var   = (const float*)d_in[13];
    float* out = (float*)d_out;

    const int write_attn = (out_size > Z_ELEMS) ? 1 : 0;
    float* attn_out = out + Z_ELEMS;

    gemm_qkv_kernel<<<NPIX / 64, 256>>>(Wq, bq, x_other, 0);  // q from x_other
    gemm_qkv_kernel<<<NPIX / 64, 256>>>(Wk, bk, x_this, 1);   // k from x_this
    gemm_qkv_kernel<<<NPIX / 64, 256>>>(Wv, bv, x_this, 2);   // v from x_this

    attn_kernel<<<2048 * 8, 128>>>(gtok, attn_out, write_attn);

    gemm_z_kernel<<<dim3(NPIX / 64, 2), 256>>>(Wz, gamma, beta, mean, var, out);
}

// round 2
// speedup vs baseline: 1.2978x; 1.2978x over previous
#include <cuda_runtime.h>

// B=8, C=256, H=W=128, IC=128, HEADS=8, WS=8, G=1, HD=16, NH=NW=16, N=64, BWIN=2048
#define HW 16384
#define NPIX 131072
#define Z_ELEMS 33554432

typedef unsigned long long ull;

// Scratch (allocation-free rule: __device__ globals)
__device__ float g_q[16777216];  // [win][head][tok][hd]
__device__ float g_k[16777216];
__device__ float g_v[16777216];
__device__ float g_o[16777216];  // attention out, spatial [b][ic][h][w]

__device__ __forceinline__ ull pack_dup(float a) {
    ull r;
    asm("mov.b64 %0, {%1, %1};" : "=l"(r) : "f"(a));
    return r;
}
__device__ __forceinline__ void ffma2(ull& acc, ull a, ull b) {
    asm("fma.rn.f32x2 %0, %1, %2, %0;" : "+l"(acc) : "l"(a), "l"(b));
}
__device__ __forceinline__ void unpack2(ull v, float& lo, float& hi) {
    asm("mov.b64 {%0, %1}, %2;" : "=f"(lo), "=f"(hi) : "l"(v));
}

// ---------------------------------------------------------------------------
// QKV projection GEMM: M=128 (oc), K=256 (c), N=131072 (pix).
// Tile 128x128x16, 256 threads, thread tile 8x8, f32x2 packed FMA.
// Writes directly in window-token layout.
// ---------------------------------------------------------------------------
__global__ void __launch_bounds__(256, 2) gemm_qkv_kernel(
    const float* __restrict__ Wm, const float* __restrict__ bias,
    const float* __restrict__ x, int sel)
{
    __shared__ float As[16][128];
    __shared__ float Bs[16][128];
    float* out = (sel == 0) ? g_q : (sel == 1) ? g_k : g_v;

    const int tid = threadIdx.x;
    const int tx = tid & 15;     // col group: cols {tx*4..+3, 64+tx*4..+3}
    const int ty = tid >> 4;     // row group: rows ty*8..+7
    const int n0 = blockIdx.x * 128;
    const int batch = n0 >> 14;
    const int hw0 = n0 & (HW - 1);
    const float* xb = x + (size_t)batch * 256 * HW + hw0;

    ull acc[8][4];
#pragma unroll
    for (int i = 0; i < 8; i++)
#pragma unroll
        for (int p = 0; p < 4; p++) acc[i][p] = 0ull;

    for (int k0 = 0; k0 < 256; k0 += 16) {
#pragma unroll
        for (int l = 0; l < 2; l++) {           // A: 128x16 transposed into As
            int f = tid * 2 + l;
            int row = f >> 2;
            int kq = f & 3;
            float4 v = *reinterpret_cast<const float4*>(&Wm[row * 256 + k0 + kq * 4]);
            As[kq * 4 + 0][row] = v.x;
            As[kq * 4 + 1][row] = v.y;
            As[kq * 4 + 2][row] = v.z;
            As[kq * 4 + 3][row] = v.w;
        }
#pragma unroll
        for (int l = 0; l < 2; l++) {           // B: 16x128 direct
            int k = tid >> 4;
            int col = (tid & 15) * 8 + l * 4;
            float4 v = *reinterpret_cast<const float4*>(&xb[(size_t)(k0 + k) * HW + col]);
            *reinterpret_cast<float4*>(&Bs[k][col]) = v;
        }
        __syncthreads();
#pragma unroll
        for (int k = 0; k < 16; k++) {
            ull bb[4];
            bb[0] = *reinterpret_cast<const ull*>(&Bs[k][tx * 4]);
            bb[1] = *reinterpret_cast<const ull*>(&Bs[k][tx * 4 + 2]);
            bb[2] = *reinterpret_cast<const ull*>(&Bs[k][64 + tx * 4]);
            bb[3] = *reinterpret_cast<const ull*>(&Bs[k][64 + tx * 4 + 2]);
            float4 a0 = *reinterpret_cast<const float4*>(&As[k][ty * 8]);
            float4 a1 = *reinterpret_cast<const float4*>(&As[k][ty * 8 + 4]);
            float a[8] = {a0.x, a0.y, a0.z, a0.w, a1.x, a1.y, a1.z, a1.w};
#pragma unroll
            for (int i = 0; i < 8; i++) {
                ull aa = pack_dup(a[i]);
#pragma unroll
                for (int p = 0; p < 4; p++) ffma2(acc[i][p], aa, bb[p]);
            }
        }
        __syncthreads();
    }

#pragma unroll
    for (int i = 0; i < 8; i++) {
        int m = ty * 8 + i;
        float bv = __ldg(&bias[m]);
        int head = m >> 4, hd = m & 15;
        float vals[8];
#pragma unroll
        for (int p = 0; p < 4; p++) unpack2(acc[i][p], vals[p * 2], vals[p * 2 + 1]);
#pragma unroll
        for (int j = 0; j < 8; j++) {
            int col = (j < 4) ? (tx * 4 + j) : (64 + tx * 4 + (j - 4));
            int hw = hw0 + col;
            int h = hw >> 7, w = hw & 127;
            int win = batch * 256 + (h >> 3) * 16 + (w >> 3);
            int tok = (h & 7) * 8 + (w & 7);
            out[(size_t)win * 8192 + head * 1024 + tok * 16 + hd] = vals[j] + bv;
        }
    }
}

// ---------------------------------------------------------------------------
// Attention: one block per (window, head). 65 rows (1 global + 64 tokens).
// ---------------------------------------------------------------------------
__global__ void __launch_bounds__(128) attn_kernel(
    const float* __restrict__ gtok, float* __restrict__ attn_out, int write_attn)
{
    __shared__ __align__(16) float Ks[65][16];
    __shared__ __align__(16) float Vs[65][16];
    __shared__ float S[65][66];

    const int tid = threadIdx.x;
    const int wh = blockIdx.x;       // win*8 + head
    const int head = wh & 7;
    const int win = wh >> 3;
    const size_t base = (size_t)wh * 1024;

    // load K,V token rows (64x16 each)
#pragma unroll
    for (int l = 0; l < 2; l++) {
        int f = tid + l * 128;
        int e = f * 4;
        int row = e >> 4;
        int col = e & 15;
        float4 kv = *reinterpret_cast<const float4*>(&g_k[base + e]);
        *reinterpret_cast<float4*>(&Ks[row + 1][col]) = kv;
        float4 vv = *reinterpret_cast<const float4*>(&g_v[base + e]);
        *reinterpret_cast<float4*>(&Vs[row + 1][col]) = vv;
    }
    if (tid < 4) {
        float4 g = *reinterpret_cast<const float4*>(&gtok[head * 16 + tid * 4]);
        *reinterpret_cast<float4*>(&Ks[0][tid * 4]) = g;
        *reinterpret_cast<float4*>(&Vs[0][tid * 4]) = g;
    }
    __syncthreads();

    // QK^T + softmax: one thread per row
    if (tid < 65) {
        float q[16];
        if (tid == 0) {
#pragma unroll
            for (int c = 0; c < 16; c++) q[c] = gtok[head * 16 + c];
        } else {
            const float* qp = &g_q[base + (size_t)(tid - 1) * 16];
#pragma unroll
            for (int c4 = 0; c4 < 4; c4++) {
                float4 v = *reinterpret_cast<const float4*>(&qp[c4 * 4]);
                q[c4 * 4 + 0] = v.x; q[c4 * 4 + 1] = v.y;
                q[c4 * 4 + 2] = v.z; q[c4 * 4 + 3] = v.w;
            }
        }
        float mx = -1e30f;
#pragma unroll 5
        for (int j = 0; j < 65; j++) {
            float4 k0 = *reinterpret_cast<const float4*>(&Ks[j][0]);
            float4 k1 = *reinterpret_cast<const float4*>(&Ks[j][4]);
            float4 k2 = *reinterpret_cast<const float4*>(&Ks[j][8]);
            float4 k3 = *reinterpret_cast<const float4*>(&Ks[j][12]);
            float d = q[0]*k0.x + q[1]*k0.y + q[2]*k0.z + q[3]*k0.w
                    + q[4]*k1.x + q[5]*k1.y + q[6]*k1.z + q[7]*k1.w
                    + q[8]*k2.x + q[9]*k2.y + q[10]*k2.z + q[11]*k2.w
                    + q[12]*k3.x + q[13]*k3.y + q[14]*k3.z + q[15]*k3.w;
            d *= 0.25f;
            S[tid][j] = d;
            mx = fmaxf(mx, d);
        }
        float sum = 0.f;
#pragma unroll 5
        for (int j = 0; j < 65; j++) {
            float e = __expf(S[tid][j] - mx);
            S[tid][j] = e;
            sum += e;
        }
        float inv = 1.f / sum;
#pragma unroll 5
        for (int j = 0; j < 65; j++) S[tid][j] *= inv;
    }
    __syncthreads();

    if (write_attn) {
        float* ap = attn_out + (size_t)wh * 4225;
        for (int e = tid; e < 4225; e += 128) {
            int r = e / 65, c2 = e - r * 65;
            ap[e] = S[r][c2];
        }
    }

    // AV: thread = (tok, 8-wide hd half). S row read ONCE; Vs as 64-bit loads.
    const int tok = tid >> 1;
    const int hd0 = (tid & 1) * 8;
    ull acc[4] = {0ull, 0ull, 0ull, 0ull};
    const float* srow = &S[tok + 1][0];
#pragma unroll 5
    for (int j = 0; j < 65; j++) {
        ull ss = pack_dup(srow[j]);
        const ull* vp = reinterpret_cast<const ull*>(&Vs[j][hd0]);
#pragma unroll
        for (int p = 0; p < 4; p++) ffma2(acc[p], ss, vp[p]);
    }
    const int b = win >> 8;
    const int wy = (win >> 4) & 15, wx = win & 15;
    const int h = wy * 8 + (tok >> 3), w = wx * 8 + (tok & 7);
    float ov[8];
#pragma unroll
    for (int p = 0; p < 4; p++) unpack2(acc[p], ov[p * 2], ov[p * 2 + 1]);
#pragma unroll
    for (int i = 0; i < 8; i++) {
        int oc = head * 16 + hd0 + i;
        g_o[(size_t)(b * 128 + oc) * HW + h * 128 + w] = ov[i];
    }
}

// ---------------------------------------------------------------------------
// z = Wz @ g_o  (M=256, K=128, N=131072) + BatchNorm epilogue -> d_out
// Tile 128x128x16, thread tile 8x8, f32x2.
// ---------------------------------------------------------------------------
__global__ void __launch_bounds__(256, 2) gemm_z_kernel(
    const float* __restrict__ Wz, const float* __restrict__ gamma,
    const float* __restrict__ beta, const float* __restrict__ mean,
    const float* __restrict__ var, float* __restrict__ out)
{
    __shared__ float As[16][128];
    __shared__ float Bs[16][128];

    const int tid = threadIdx.x;
    const int tx = tid & 15;
    const int ty = tid >> 4;
    const int n0 = blockIdx.x * 128;
    const int m0 = blockIdx.y * 128;
    const int batch = n0 >> 14;
    const int hw0 = n0 & (HW - 1);
    const float* xb = g_o + (size_t)batch * 128 * HW + hw0;

    ull acc[8][4];
#pragma unroll
    for (int i = 0; i < 8; i++)
#pragma unroll
        for (int p = 0; p < 4; p++) acc[i][p] = 0ull;

    for (int k0 = 0; k0 < 128; k0 += 16) {
#pragma unroll
        for (int l = 0; l < 2; l++) {
            int f = tid * 2 + l;
            int row = f >> 2;
            int kq = f & 3;
            float4 v = *reinterpret_cast<const float4*>(&Wz[(m0 + row) * 128 + k0 + kq * 4]);
            As[kq * 4 + 0][row] = v.x;
            As[kq * 4 + 1][row] = v.y;
            As[kq * 4 + 2][row] = v.z;
            As[kq * 4 + 3][row] = v.w;
        }
#pragma unroll
        for (int l = 0; l < 2; l++) {
            int k = tid >> 4;
            int col = (tid & 15) * 8 + l * 4;
            float4 v = *reinterpret_cast<const float4*>(&xb[(size_t)(k0 + k) * HW + col]);
            *reinterpret_cast<float4*>(&Bs[k][col]) = v;
        }
        __syncthreads();
#pragma unroll
        for (int k = 0; k < 16; k++) {
            ull bb[4];
            bb[0] = *reinterpret_cast<const ull*>(&Bs[k][tx * 4]);
            bb[1] = *reinterpret_cast<const ull*>(&Bs[k][tx * 4 + 2]);
            bb[2] = *reinterpret_cast<const ull*>(&Bs[k][64 + tx * 4]);
            bb[3] = *reinterpret_cast<const ull*>(&Bs[k][64 + tx * 4 + 2]);
            float4 a0 = *reinterpret_cast<const float4*>(&As[k][ty * 8]);
            float4 a1 = *reinterpret_cast<const float4*>(&As[k][ty * 8 + 4]);
            float a[8] = {a0.x, a0.y, a0.z, a0.w, a1.x, a1.y, a1.z, a1.w};
#pragma unroll
            for (int i = 0; i < 8; i++) {
                ull aa = pack_dup(a[i]);
#pragma unroll
                for (int p = 0; p < 4; p++) ffma2(acc[i][p], aa, bb[p]);
            }
        }
        __syncthreads();
    }

#pragma unroll
    for (int i = 0; i < 8; i++) {
        int oc = m0 + ty * 8 + i;
        float sc = __ldg(&gamma[oc]) * rsqrtf(__ldg(&var[oc]) + 1e-5f);
        float sh = __ldg(&beta[oc]) - __ldg(&mean[oc]) * sc;
        float vals[8];
#pragma unroll
        for (int p = 0; p < 4; p++) unpack2(acc[i][p], vals[p * 2], vals[p * 2 + 1]);
        float4 r0, r1;
        r0.x = vals[0] * sc + sh; r0.y = vals[1] * sc + sh;
        r0.z = vals[2] * sc + sh; r0.w = vals[3] * sc + sh;
        r1.x = vals[4] * sc + sh; r1.y = vals[5] * sc + sh;
        r1.z = vals[6] * sc + sh; r1.w = vals[7] * sc + sh;
        float* op = &out[(size_t)(batch * 256 + oc) * HW + hw0];
        *reinterpret_cast<float4*>(&op[tx * 4]) = r0;
        *reinterpret_cast<float4*>(&op[64 + tx * 4]) = r1;
    }
}

// ---------------------------------------------------------------------------
extern "C" void kernel_launch(void* const* d_in, const int* in_sizes, int n_in,
                              void* d_out, int out_size)
{
    const float* x_this  = (const float*)d_in[0];
    const float* x_other = (const float*)d_in[1];
    const float* Wq = (const float*)d_in[2];
    const float* bq = (const float*)d_in[3];
    const float* Wk = (const float*)d_in[4];
    const float* bk = (const float*)d_in[5];
    const float* Wv = (const float*)d_in[6];
    const float* bv = (const float*)d_in[7];
    const float* gtok = (const float*)d_in[8];
    const float* Wz = (const float*)d_in[9];
    const float* gamma = (const float*)d_in[10];
    const float* beta  = (const float*)d_in[11];
    const float* mean  = (const float*)d_in[12];
    const float* var   = (const float*)d_in[13];
    float* out = (float*)d_out;

    const int write_attn = (out_size > Z_ELEMS) ? 1 : 0;
    float* attn_out = out + Z_ELEMS;

    gemm_qkv_kernel<<<NPIX / 128, 256>>>(Wq, bq, x_other, 0);
    gemm_qkv_kernel<<<NPIX / 128, 256>>>(Wk, bk, x_this, 1);
    gemm_qkv_kernel<<<NPIX / 128, 256>>>(Wv, bv, x_this, 2);

    attn_kernel<<<2048 * 8, 128>>>(gtok, attn_out, write_attn);

    gemm_z_kernel<<<dim3(NPIX / 128, 2), 256>>>(Wz, gamma, beta, mean, var, out);
}

// round 4
// speedup vs baseline: 2.1419x; 1.6504x over previous
#include <cuda_runtime.h>
#include <cuda_bf16.h>
#include <cstdint>

// B=8, C=256, H=W=128, IC=128, HEADS=8, WS=8, G=1, HD=16, N=64, BWIN=2048
#define HW 16384
#define NPIX 131072
#define Z_ELEMS 33554432

typedef unsigned long long ull;

// Scratch (allocation-free rule: __device__ globals)
__device__ float g_q[16777216];  // [win][head][tok][hd]
__device__ float g_k[16777216];
__device__ float g_v[16777216];
__device__ float g_o[16777216];  // attention out, spatial [b][ic][h][w]

// ---------------- helpers ----------------
__device__ __forceinline__ uint32_t smem_u32(const void* p) {
    uint32_t a;
    asm("{ .reg .u64 t; cvta.to.shared.u64 t, %1; cvt.u32.u64 %0, t; }" : "=r"(a) : "l"(p));
    return a;
}
__device__ __forceinline__ ull pack_dup(float a) {
    ull r; asm("mov.b64 %0, {%1, %1};" : "=l"(r) : "f"(a)); return r;
}
__device__ __forceinline__ void ffma2(ull& acc, ull a, ull b) {
    asm("fma.rn.f32x2 %0, %1, %2, %0;" : "+l"(acc) : "l"(a), "l"(b));
}
__device__ __forceinline__ void unpack2(ull v, float& lo, float& hi) {
    asm("mov.b64 {%0, %1}, %2;" : "=f"(lo), "=f"(hi) : "l"(v));
}

// hi/lo bf16 split of two floats, packed as bf16x2 words
__device__ __forceinline__ void split2(float a, float b, uint32_t& h, uint32_t& l) {
    __nv_bfloat16 ha = __float2bfloat16_rn(a), hb = __float2bfloat16_rn(b);
    float la = a - __bfloat162float(ha), lb = b - __bfloat162float(hb);
    __nv_bfloat162 hh(ha, hb);
    __nv_bfloat162 ll(__float2bfloat16_rn(la), __float2bfloat16_rn(lb));
    h = *reinterpret_cast<uint32_t*>(&hh);
    l = *reinterpret_cast<uint32_t*>(&ll);
}

__device__ __forceinline__ void ldsm_x4(uint32_t (&r)[4], uint32_t addr) {
    asm volatile("ldmatrix.sync.aligned.m8n8.x4.shared.b16 {%0,%1,%2,%3}, [%4];"
        : "=r"(r[0]), "=r"(r[1]), "=r"(r[2]), "=r"(r[3]) : "r"(addr));
}
__device__ __forceinline__ void mma_bf16(float (&d)[4], const uint32_t (&a)[4],
                                         uint32_t b0, uint32_t b1) {
    asm volatile("mma.sync.aligned.m16n8k16.row.col.f32.bf16.bf16.f32 "
        "{%0,%1,%2,%3}, {%4,%5,%6,%7}, {%8,%9}, {%0,%1,%2,%3};"
        : "+f"(d[0]), "+f"(d[1]), "+f"(d[2]), "+f"(d[3])
        : "r"(a[0]), "r"(a[1]), "r"(a[2]), "r"(a[3]), "r"(b0), "r"(b1));
}

#define SWZ(o) ((o) ^ (((o) >> 3) & 0x70))

// SMEM: four 16KB bf16 tiles (128 rows x 64 k, 128B pitch); stage reuses from 0
#define A_HI 0
#define A_LO 16384
#define B_HI 32768
#define B_LO 49152
#define SMEM_GEMM 67584   // stage: 128 * 132 * 4 bytes

// ---------------------------------------------------------------------------
// Shared GEMM mainloop body: computes 128(M) x 128(N) with K = nchunks*64.
// acc[mi][ni][4]. Caller stages A/B tiles per chunk.
// ---------------------------------------------------------------------------
struct WarpCtx {
    int m0w, n0w;        // warp tile origin
    int a_row, a_k;      // ldmatrix lane row/k offsets for A
    int b_row, b_k;      // for B
};

__device__ __forceinline__ void mma_chunk(
    float (&acc)[4][4][4], const WarpCtx& c, uint32_t sb)
{
#pragma unroll
    for (int ks = 0; ks < 4; ks++) {
        const int k0 = ks * 16;
        uint32_t Af[4][4], Bf[2][4];
        // A hi
#pragma unroll
        for (int mi = 0; mi < 4; mi++)
            ldsm_x4(Af[mi], sb + A_HI +
                SWZ((uint32_t)((c.m0w + mi * 16 + c.a_row) * 128 + (k0 + c.a_k) * 2)));
        // B lo
#pragma unroll
        for (int bi = 0; bi < 2; bi++)
            ldsm_x4(Bf[bi], sb + B_LO +
                SWZ((uint32_t)((c.n0w + bi * 16 + c.b_row) * 128 + (k0 + c.b_k) * 2)));
#pragma unroll
        for (int mi = 0; mi < 4; mi++)
#pragma unroll
            for (int ni = 0; ni < 4; ni++)
                mma_bf16(acc[mi][ni], Af[mi], Bf[ni >> 1][(ni & 1) * 2], Bf[ni >> 1][(ni & 1) * 2 + 1]);
        // B hi
#pragma unroll
        for (int bi = 0; bi < 2; bi++)
            ldsm_x4(Bf[bi], sb + B_HI +
                SWZ((uint32_t)((c.n0w + bi * 16 + c.b_row) * 128 + (k0 + c.b_k) * 2)));
#pragma unroll
        for (int mi = 0; mi < 4; mi++)
#pragma unroll
            for (int ni = 0; ni < 4; ni++)
                mma_bf16(acc[mi][ni], Af[mi], Bf[ni >> 1][(ni & 1) * 2], Bf[ni >> 1][(ni & 1) * 2 + 1]);
        // A lo
#pragma unroll
        for (int mi = 0; mi < 4; mi++)
            ldsm_x4(Af[mi], sb + A_LO +
                SWZ((uint32_t)((c.m0w + mi * 16 + c.a_row) * 128 + (k0 + c.a_k) * 2)));
#pragma unroll
        for (int mi = 0; mi < 4; mi++)
#pragma unroll
            for (int ni = 0; ni < 4; ni++)
                mma_bf16(acc[mi][ni], Af[mi], Bf[ni >> 1][(ni & 1) * 2], Bf[ni >> 1][(ni & 1) * 2 + 1]);
    }
}

// Stage B chunk (64 k-rows x 128 pixels) from channel-major global into
// K-major swizzled bf16 hi/lo tiles, via register 4x4 transpose.
__device__ __forceinline__ void stage_B(char* smem, const float* xb, int c0,
                                        int nq, int kb)
{
#pragma unroll
    for (int g = 0; g < 2; g++) {
        float a[4][4];
#pragma unroll
        for (int j4 = 0; j4 < 4; j4++) {
            float4 v = *reinterpret_cast<const float4*>(
                &xb[(size_t)(c0 + kb * 8 + g * 4 + j4) * HW + nq * 4]);
            a[j4][0] = v.x; a[j4][1] = v.y; a[j4][2] = v.z; a[j4][3] = v.w;
        }
#pragma unroll
        for (int j = 0; j < 4; j++) {
            uint32_t h0, l0, h1, l1;
            split2(a[0][j], a[1][j], h0, l0);
            split2(a[2][j], a[3][j], h1, l1);
            uint32_t off = SWZ((uint32_t)((nq * 4 + j) * 128 + kb * 16 + g * 8));
            *reinterpret_cast<uint2*>(smem + B_HI + off) = make_uint2(h0, h1);
            *reinterpret_cast<uint2*>(smem + B_LO + off) = make_uint2(l0, l1);
        }
    }
}

// ---------------------------------------------------------------------------
// QKV GEMM: M=128 oc, K=256, N=128 pixels/block. Writes window-token layout.
// ---------------------------------------------------------------------------
__global__ void __launch_bounds__(256, 2) gemm_qkv_mma(
    const float* __restrict__ W, const float* __restrict__ bias,
    const float* __restrict__ x, int sel)
{
    extern __shared__ char smem[];
    float* out = (sel == 0) ? g_q : (sel == 1) ? g_k : g_v;
    const int tid = threadIdx.x, wid = tid >> 5, lane = tid & 31;
    const int gid = lane >> 2, tig = lane & 3;
    const uint32_t sb = smem_u32(smem);

    const int n0 = blockIdx.x * 128;
    const int batch = n0 >> 14, hw0 = n0 & (HW - 1);
    const float* xb = x + (size_t)batch * 256 * HW + hw0;
    const int nq = tid & 31, kb = tid >> 5;

    WarpCtx c;
    c.m0w = (wid >> 2) * 64;
    c.n0w = (wid & 3) * 32;
    c.a_row = ((lane >> 3) & 1) * 8 + (lane & 7);
    c.a_k   = (lane >> 4) * 8;
    c.b_row = ((lane >> 4) & 1) * 8 + (lane & 7);
    c.b_k   = ((lane >> 3) & 1) * 8;

    float acc[4][4][4];
#pragma unroll
    for (int mi = 0; mi < 4; mi++)
#pragma unroll
        for (int ni = 0; ni < 4; ni++)
#pragma unroll
            for (int e = 0; e < 4; e++) acc[mi][ni][e] = 0.f;

    for (int ch = 0; ch < 4; ch++) {
        const int c0 = ch * 64;
        __syncthreads();
        // A: W[128][64 cols]
#pragma unroll
        for (int it = 0; it < 8; it++) {
            int f = tid + it * 256;
            int row = f >> 4, cq = f & 15;
            float4 v = *reinterpret_cast<const float4*>(&W[row * 256 + c0 + cq * 4]);
            uint32_t h0, l0, h1, l1;
            split2(v.x, v.y, h0, l0);
            split2(v.z, v.w, h1, l1);
            uint32_t off = SWZ((uint32_t)(row * 128 + cq * 8));
            *reinterpret_cast<uint2*>(smem + A_HI + off) = make_uint2(h0, h1);
            *reinterpret_cast<uint2*>(smem + A_LO + off) = make_uint2(l0, l1);
        }
        stage_B(smem, xb, c0, nq, kb);
        __syncthreads();
        mma_chunk(acc, c, sb);
    }

    // Epilogue: stage [pix][132] with bias, then window-layout float4 stores
    __syncthreads();
    float* stage = reinterpret_cast<float*>(smem);
#pragma unroll
    for (int mi = 0; mi < 4; mi++) {
        int r0 = c.m0w + mi * 16 + gid, r1 = r0 + 8;
        float bv0 = __ldg(&bias[r0]), bv1 = __ldg(&bias[r1]);
#pragma unroll
        for (int ni = 0; ni < 4; ni++) {
            int col = c.n0w + ni * 8 + 2 * tig;
            stage[col * 132 + r0]       = acc[mi][ni][0] + bv0;
            stage[(col + 1) * 132 + r0] = acc[mi][ni][1] + bv0;
            stage[col * 132 + r1]       = acc[mi][ni][2] + bv1;
            stage[(col + 1) * 132 + r1] = acc[mi][ni][3] + bv1;
        }
    }
    __syncthreads();
#pragma unroll
    for (int it = 0; it < 16; it++) {
        int jj = tid + it * 256;
        int pix = jj >> 5, f4 = jj & 31;
        float4 v = *reinterpret_cast<float4*>(&stage[pix * 132 + f4 * 4]);
        int hw = hw0 + pix, h = hw >> 7, w = hw & 127;
        int win = batch * 256 + (h >> 3) * 16 + (w >> 3);
        int tok = (h & 7) * 8 + (w & 7);
        int head = f4 >> 2, hd0 = (f4 & 3) * 4;
        *reinterpret_cast<float4*>(&out[(size_t)win * 8192 + head * 1024 + tok * 16 + hd0]) = v;
    }
}

// ---------------------------------------------------------------------------
// z GEMM: M=256 (grid.y of 2 x 128), K=128, N=128 pixels/block, + BatchNorm.
// ---------------------------------------------------------------------------
__global__ void __launch_bounds__(256, 2) gemm_z_mma(
    const float* __restrict__ Wz, const float* __restrict__ gamma,
    const float* __restrict__ beta, const float* __restrict__ mean,
    const float* __restrict__ var, float* __restrict__ out)
{
    extern __shared__ char smem[];
    const int tid = threadIdx.x, wid = tid >> 5, lane = tid & 31;
    const int gid = lane >> 2, tig = lane & 3;
    const uint32_t sb = smem_u32(smem);

    const int n0 = blockIdx.x * 128;
    const int m0 = blockIdx.y * 128;
    const int batch = n0 >> 14, hw0 = n0 & (HW - 1);
    const float* xb = g_o + (size_t)batch * 128 * HW + hw0;
    const int nq = tid & 31, kb = tid >> 5;

    WarpCtx c;
    c.m0w = (wid >> 2) * 64;
    c.n0w = (wid & 3) * 32;
    c.a_row = ((lane >> 3) & 1) * 8 + (lane & 7);
    c.a_k   = (lane >> 4) * 8;
    c.b_row = ((lane >> 4) & 1) * 8 + (lane & 7);
    c.b_k   = ((lane >> 3) & 1) * 8;

    float acc[4][4][4];
#pragma unroll
    for (int mi = 0; mi < 4; mi++)
#pragma unroll
        for (int ni = 0; ni < 4; ni++)
#pragma unroll
            for (int e = 0; e < 4; e++) acc[mi][ni][e] = 0.f;

    for (int ch = 0; ch < 2; ch++) {
        const int c0 = ch * 64;
        __syncthreads();
#pragma unroll
        for (int it = 0; it < 8; it++) {
            int f = tid + it * 256;
            int row = f >> 4, cq = f & 15;
            float4 v = *reinterpret_cast<const float4*>(&Wz[(m0 + row) * 128 + c0 + cq * 4]);
            uint32_t h0, l0, h1, l1;
            split2(v.x, v.y, h0, l0);
            split2(v.z, v.w, h1, l1);
            uint32_t off = SWZ((uint32_t)(row * 128 + cq * 8));
            *reinterpret_cast<uint2*>(smem + A_HI + off) = make_uint2(h0, h1);
            *reinterpret_cast<uint2*>(smem + A_LO + off) = make_uint2(l0, l1);
        }
        stage_B(smem, xb, c0, nq, kb);
        __syncthreads();
        mma_chunk(acc, c, sb);
    }

    // Epilogue: BN applied, stage [oc][132], coalesced channel-major stores
    __syncthreads();
    float* stage = reinterpret_cast<float*>(smem);
#pragma unroll
    for (int mi = 0; mi < 4; mi++) {
        int r0 = c.m0w + mi * 16 + gid, r1 = r0 + 8;
        int oc0 = m0 + r0, oc1 = m0 + r1;
        float sc0 = __ldg(&gamma[oc0]) * rsqrtf(__ldg(&var[oc0]) + 1e-5f);
        float sh0 = __ldg(&beta[oc0]) - __ldg(&mean[oc0]) * sc0;
        float sc1 = __ldg(&gamma[oc1]) * rsqrtf(__ldg(&var[oc1]) + 1e-5f);
        float sh1 = __ldg(&beta[oc1]) - __ldg(&mean[oc1]) * sc1;
#pragma unroll
        for (int ni = 0; ni < 4; ni++) {
            int col = c.n0w + ni * 8 + 2 * tig;
            float2 p0 = make_float2(acc[mi][ni][0] * sc0 + sh0, acc[mi][ni][1] * sc0 + sh0);
            float2 p1 = make_float2(acc[mi][ni][2] * sc1 + sh1, acc[mi][ni][3] * sc1 + sh1);
            *reinterpret_cast<float2*>(&stage[r0 * 132 + col]) = p0;
            *reinterpret_cast<float2*>(&stage[r1 * 132 + col]) = p1;
        }
    }
    __syncthreads();
#pragma unroll
    for (int it = 0; it < 16; it++) {
        int jj = tid + it * 256;
        int ocl = jj >> 5, cf = jj & 31;
        float4 v = *reinterpret_cast<float4*>(&stage[ocl * 132 + cf * 4]);
        *reinterpret_cast<float4*>(
            &out[(size_t)(batch * 256 + m0 + ocl) * HW + hw0 + cf * 4]) = v;
    }
}

// ---------------------------------------------------------------------------
// Attention: one block per (window, head). Softmax pass-3 folded into Sinv.
// ---------------------------------------------------------------------------
__global__ void __launch_bounds__(128) attn_kernel(
    const float* __restrict__ gtok, float* __restrict__ attn_out, int write_attn)
{
    __shared__ __align__(16) float Ks[65][16];
    __shared__ __align__(16) float Vs[65][16];
    __shared__ float S[65][66];
    __shared__ float Sinv[65];

    const int tid = threadIdx.x;
    const int wh = blockIdx.x;
    const int head = wh & 7;
    const int win = wh >> 3;
    const size_t base = (size_t)wh * 1024;

#pragma unroll
    for (int l = 0; l < 2; l++) {
        int f = tid + l * 128;
        int e = f * 4;
        int row = e >> 4;
        int col = e & 15;
        float4 kv = *reinterpret_cast<const float4*>(&g_k[base + e]);
        *reinterpret_cast<float4*>(&Ks[row + 1][col]) = kv;
        float4 vv = *reinterpret_cast<const float4*>(&g_v[base + e]);
        *reinterpret_cast<float4*>(&Vs[row + 1][col]) = vv;
    }
    if (tid < 4) {
        float4 g = *reinterpret_cast<const float4*>(&gtok[head * 16 + tid * 4]);
        *reinterpret_cast<float4*>(&Ks[0][tid * 4]) = g;
        *reinterpret_cast<float4*>(&Vs[0][tid * 4]) = g;
    }
    __syncthreads();

    if (tid < 65) {
        float q[16];
        if (tid == 0) {
#pragma unroll
            for (int c = 0; c < 16; c++) q[c] = gtok[head * 16 + c];
        } else {
            const float* qp = &g_q[base + (size_t)(tid - 1) * 16];
#pragma unroll
            for (int c4 = 0; c4 < 4; c4++) {
                float4 v = *reinterpret_cast<const float4*>(&qp[c4 * 4]);
                q[c4 * 4 + 0] = v.x; q[c4 * 4 + 1] = v.y;
                q[c4 * 4 + 2] = v.z; q[c4 * 4 + 3] = v.w;
            }
        }
        float mx = -1e30f;
#pragma unroll 5
        for (int j = 0; j < 65; j++) {
            float4 k0 = *reinterpret_cast<const float4*>(&Ks[j][0]);
            float4 k1 = *reinterpret_cast<const float4*>(&Ks[j][4]);
            float4 k2 = *reinterpret_cast<const float4*>(&Ks[j][8]);
            float4 k3 = *reinterpret_cast<const float4*>(&Ks[j][12]);
            float d = q[0]*k0.x + q[1]*k0.y + q[2]*k0.z + q[3]*k0.w
                    + q[4]*k1.x + q[5]*k1.y + q[6]*k1.z + q[7]*k1.w
                    + q[8]*k2.x + q[9]*k2.y + q[10]*k2.z + q[11]*k2.w
                    + q[12]*k3.x + q[13]*k3.y + q[14]*k3.z + q[15]*k3.w;
            d *= 0.25f;
            S[tid][j] = d;
            mx = fmaxf(mx, d);
        }
        float sum = 0.f;
#pragma unroll 5
        for (int j = 0; j < 65; j++) {
            float e = __expf(S[tid][j] - mx);
            S[tid][j] = e;
            sum += e;
        }
        Sinv[tid] = 1.f / sum;
    }
    __syncthreads();

    if (write_attn) {
        float* ap = attn_out + (size_t)wh * 4225;
        for (int e = tid; e < 4225; e += 128) {
            int r = e / 65, c2 = e - r * 65;
            ap[e] = S[r][c2] * Sinv[r];
        }
    }

    const int tok = tid >> 1;
    const int hd0 = (tid & 1) * 8;
    ull acc[4] = {0ull, 0ull, 0ull, 0ull};
    const float* srow = &S[tok + 1][0];
#pragma unroll 5
    for (int j = 0; j < 65; j++) {
        ull ss = pack_dup(srow[j]);
        const ull* vp = reinterpret_cast<const ull*>(&Vs[j][hd0]);
#pragma unroll
        for (int p = 0; p < 4; p++) ffma2(acc[p], ss, vp[p]);
    }
    const float inv = Sinv[tok + 1];
    const int b = win >> 8;
    const int wy = (win >> 4) & 15, wx = win & 15;
    const int h = wy * 8 + (tok >> 3), w = wx * 8 + (tok & 7);
    float ov[8];
#pragma unroll
    for (int p = 0; p < 4; p++) unpack2(acc[p], ov[p * 2], ov[p * 2 + 1]);
#pragma unroll
    for (int i = 0; i < 8; i++) {
        int oc = head * 16 + hd0 + i;
        g_o[(size_t)(b * 128 + oc) * HW + h * 128 + w] = ov[i] * inv;
    }
}

// ---------------------------------------------------------------------------
extern "C" void kernel_launch(void* const* d_in, const int* in_sizes, int n_in,
                              void* d_out, int out_size)
{
    const float* x_this  = (const float*)d_in[0];
    const float* x_other = (const float*)d_in[1];
    const float* Wq = (const float*)d_in[2];
    const float* bq = (const float*)d_in[3];
    const float* Wk = (const float*)d_in[4];
    const float* bk = (const float*)d_in[5];
    const float* Wv = (const float*)d_in[6];
    const float* bv = (const float*)d_in[7];
    const float* gtok = (const float*)d_in[8];
    const float* Wz = (const float*)d_in[9];
    const float* gamma = (const float*)d_in[10];
    const float* beta  = (const float*)d_in[11];
    const float* mean  = (const float*)d_in[12];
    const float* var   = (const float*)d_in[13];
    float* out = (float*)d_out;

    const int write_attn = (out_size > Z_ELEMS) ? 1 : 0;
    float* attn_out = out + Z_ELEMS;

    static int attr_done = 0;
    if (!attr_done) {
        cudaFuncSetAttribute((const void*)gemm_qkv_mma,
                             cudaFuncAttributeMaxDynamicSharedMemorySize, SMEM_GEMM);
        cudaFuncSetAttribute((const void*)gemm_z_mma,
                             cudaFuncAttributeMaxDynamicSharedMemorySize, SMEM_GEMM);
        attr_done = 1;
    }

    gemm_qkv_mma<<<NPIX / 128, 256, SMEM_GEMM>>>(Wq, bq, x_other, 0);
    gemm_qkv_mma<<<NPIX / 128, 256, SMEM_GEMM>>>(Wk, bk, x_this, 1);
    gemm_qkv_mma<<<NPIX / 128, 256, SMEM_GEMM>>>(Wv, bv, x_this, 2);

    attn_kernel<<<2048 * 8, 128>>>(gtok, attn_out, write_attn);

    gemm_z_mma<<<dim3(NPIX / 128, 2), 256, SMEM_GEMM>>>(Wz, gamma, beta, mean, var, out);
}